// round 1
// baseline (speedup 1.0000x reference)
#include <cuda_runtime.h>

#define PTOT (32*512*512)   // 8388608 voxels
#define C 16                // channels
#define NL 64               // segment labels

// ---- persistent device scratch (static allocation: allowed) ----
__device__ float g_sums[C*NL];          // [c*NL + s]
__device__ float g_counts[NL];
__device__ float g_means[NL*C];         // [s*C + c]
__device__ float g_w[NL];               // present ? 1/(count*K) : 0
__device__ float g_ext_nrm;             // BETA*loss_ext + GAMMA*loss_nrm
__device__ double g_int;                // weighted sum of margin^2
__device__ unsigned char g_seg[PTOT];   // cached labels for pass 2

// ---------------- init: zero accumulators (replay-safe) ----------------
__global__ void k_init() {
    int i = threadIdx.x;                // 1024 threads
    g_sums[i] = 0.f;
    if (i < NL) g_counts[i] = 0.f;
    if (i == 0) g_int = 0.0;
}

// ---------------- pass 1: segment sums + counts + seg cache ----------------
__global__ __launch_bounds__(256) void k_pass1(const float* __restrict__ embd,
                                               const int*   __restrict__ trgt,
                                               const int*   __restrict__ mask) {
    __shared__ float sb[C*NL];          // [c*NL + s] -> bank = s%32 (spread)
    __shared__ float sc[NL];
    int tid = threadIdx.x;
    #pragma unroll
    for (int i = tid; i < C*NL; i += 256) sb[i] = 0.f;
    if (tid < NL) sc[tid] = 0.f;
    __syncthreads();

    size_t base = ((size_t)blockIdx.x * 256 + tid) * 4;   // 4 voxels/thread
    int4 t4 = *reinterpret_cast<const int4*>(trgt + base);
    int4 m4 = *reinterpret_cast<const int4*>(mask + base);
    int s0 = (m4.x > 0) ? t4.x : 0;
    int s1 = (m4.y > 0) ? t4.y : 0;
    int s2 = (m4.z > 0) ? t4.z : 0;
    int s3 = (m4.w > 0) ? t4.w : 0;
    *reinterpret_cast<uchar4*>(g_seg + base) =
        make_uchar4((unsigned char)s0, (unsigned char)s1,
                    (unsigned char)s2, (unsigned char)s3);

    atomicAdd(&sc[s0], 1.f);
    atomicAdd(&sc[s1], 1.f);
    atomicAdd(&sc[s2], 1.f);
    atomicAdd(&sc[s3], 1.f);

    #pragma unroll
    for (int c = 0; c < C; c++) {
        float4 v = *reinterpret_cast<const float4*>(embd + (size_t)c * PTOT + base);
        atomicAdd(&sb[c*NL + s0], v.x);
        atomicAdd(&sb[c*NL + s1], v.y);
        atomicAdd(&sb[c*NL + s2], v.z);
        atomicAdd(&sb[c*NL + s3], v.w);
    }
    __syncthreads();

    for (int i = tid; i < C*NL; i += 256) atomicAdd(&g_sums[i], sb[i]);
    if (tid < NL) atomicAdd(&g_counts[tid], sc[tid]);
}

// ---------------- stats: means, K, weights, ext + nrm terms ----------------
__global__ void k_stats() {
    __shared__ float sm[NL][C];
    __shared__ float sext[NL];
    __shared__ float snrm[NL];
    __shared__ int   spres[NL];
    __shared__ float sK;
    int s = threadIdx.x;                // 64 threads
    float cnt  = g_counts[s];
    int   pres = (cnt > 0.f) && (s != 0);
    float safe = fmaxf(cnt, 1.f);
    #pragma unroll
    for (int c = 0; c < C; c++) {
        float m = g_sums[c*NL + s] / safe;
        sm[s][c] = m;
        g_means[s*C + c] = m;
    }
    spres[s] = pres;
    __syncthreads();
    if (s == 0) {
        int k = 0;
        for (int l = 0; l < NL; l++) k += spres[l];
        sK = (float)k;
    }
    __syncthreads();
    float K = sK;
    g_w[s] = pres ? 1.f / (safe * fmaxf(K, 1.f)) : 0.f;

    float nrm = 0.f, ext = 0.f;
    if (pres) {
        #pragma unroll
        for (int c = 0; c < C; c++) nrm += fabsf(sm[s][c]);
        for (int j = 0; j < NL; j++) {
            if (j != s && spres[j]) {
                float d = 0.f;
                #pragma unroll
                for (int c = 0; c < C; c++) d += fabsf(sm[s][c] - sm[j][c]);
                float m = fmaxf(3.0f - d, 0.f);   // 2*DELTA_D = 3.0
                ext += m * m;
            }
        }
    }
    sext[s] = ext; snrm[s] = nrm;
    __syncthreads();
    if (s == 0) {
        float esum = 0.f, nsum = 0.f;
        for (int l = 0; l < NL; l++) { esum += sext[l]; nsum += snrm[l]; }
        float loss_ext = esum / fmaxf(1.f, K * (K - 1.f));
        float loss_nrm = nsum / fmaxf(1.f, K);
        g_ext_nrm = 1.0f * loss_ext + 0.001f * loss_nrm;   // BETA, GAMMA
    }
}

// ---------------- pass 2: internal term ----------------
__global__ __launch_bounds__(256) void k_pass2(const float* __restrict__ embd) {
    __shared__ float smean[NL*C];       // [s*C + c]
    __shared__ float sw[NL];
    __shared__ float sred[256];
    int tid = threadIdx.x;
    for (int i = tid; i < NL*C; i += 256) smean[i] = g_means[i];
    if (tid < NL) sw[tid] = g_w[tid];
    __syncthreads();

    size_t base = ((size_t)blockIdx.x * 256 + tid) * 4;
    uchar4 sv = *reinterpret_cast<const uchar4*>(g_seg + base);
    const float4* m0 = reinterpret_cast<const float4*>(&smean[sv.x * C]);
    const float4* m1 = reinterpret_cast<const float4*>(&smean[sv.y * C]);
    const float4* m2 = reinterpret_cast<const float4*>(&smean[sv.z * C]);
    const float4* m3 = reinterpret_cast<const float4*>(&smean[sv.w * C]);

    float g0 = 0.f, g1 = 0.f, g2 = 0.f, g3 = 0.f;
    #pragma unroll
    for (int cg = 0; cg < 4; cg++) {
        float4 a0 = m0[cg], a1 = m1[cg], a2 = m2[cg], a3 = m3[cg];
        float4 v0 = *reinterpret_cast<const float4*>(embd + (size_t)(cg*4+0) * PTOT + base);
        float4 v1 = *reinterpret_cast<const float4*>(embd + (size_t)(cg*4+1) * PTOT + base);
        float4 v2 = *reinterpret_cast<const float4*>(embd + (size_t)(cg*4+2) * PTOT + base);
        float4 v3 = *reinterpret_cast<const float4*>(embd + (size_t)(cg*4+3) * PTOT + base);
        g0 += fabsf(v0.x - a0.x) + fabsf(v1.x - a0.y) + fabsf(v2.x - a0.z) + fabsf(v3.x - a0.w);
        g1 += fabsf(v0.y - a1.x) + fabsf(v1.y - a1.y) + fabsf(v2.y - a1.z) + fabsf(v3.y - a1.w);
        g2 += fabsf(v0.z - a2.x) + fabsf(v1.z - a2.y) + fabsf(v2.z - a2.z) + fabsf(v3.z - a2.w);
        g3 += fabsf(v0.w - a3.x) + fabsf(v1.w - a3.y) + fabsf(v2.w - a3.z) + fabsf(v3.w - a3.w);
    }
    // DELTA_V = 0 and margin >= 0, so hinge is the identity; just square.
    float acc = sw[sv.x]*g0*g0 + sw[sv.y]*g1*g1 + sw[sv.z]*g2*g2 + sw[sv.w]*g3*g3;

    sred[tid] = acc;
    __syncthreads();
    #pragma unroll
    for (int off = 128; off > 0; off >>= 1) {
        if (tid < off) sred[tid] += sred[tid + off];
        __syncthreads();
    }
    if (tid == 0) atomicAdd(&g_int, (double)sred[0]);
}

// ---------------- final combine ----------------
__global__ void k_final(float* out) {
    out[0] = (float)g_int + g_ext_nrm;   // ALPHA = 1
}

extern "C" void kernel_launch(void* const* d_in, const int* in_sizes, int n_in,
                              void* d_out, int out_size) {
    const float* embd = (const float*)d_in[0];
    const int*   trgt = (const int*)d_in[1];
    const int*   mask = (const int*)d_in[2];
    float* out = (float*)d_out;

    k_init <<<1, 1024>>>();
    k_pass1<<<PTOT/1024, 256>>>(embd, trgt, mask);
    k_stats<<<1, NL>>>();
    k_pass2<<<PTOT/1024, 256>>>(embd);
    k_final<<<1, 1>>>(out);
}

// round 3
// speedup vs baseline: 5.3739x; 5.3739x over previous
#include <cuda_runtime.h>
#include <cstdint>

#define PTOT (32*512*512)        // 8388608 voxels
#define C 16
#define NL 64
#define NCOL 17                  // 16 channel sums + count

// ---- pass1 tiling ----
#define P1_BLOCKS 1024
#define VOX_PER_CTA (PTOT/P1_BLOCKS)   // 8192
#define TILE_V 512
#define NTILES (VOX_PER_CTA/TILE_V)    // 16
#define P1_THREADS 256
#define NW 8                           // warps per CTA

// shared layout (words): [buckets][xtile][segtile]
#define BKT_WPW 2048                   // per-warp bucket words: 64 segs * 16 ch * 2 halves
#define BKT_WORDS (NW*BKT_WPW)         // 16384 words = 64 KB
#define XT_STRIDE 518                  // padded words per channel row (bank-conflict-free)
#define XT_WORDS (C*XT_STRIDE)         // 8288 words
#define P1_SMEM_WORDS (BKT_WORDS + XT_WORDS + 128)
#define P1_SMEM_BYTES (P1_SMEM_WORDS*4)   // 99200 B -> 2 CTAs/SM

// ---- k_seg ----
#define SEG_BLOCKS 1024
#define SEG_VOX (PTOT/SEG_BLOCKS)      // 8192
#define SEG_SMEM_BYTES (NW*2048*4)     // 64 KB

// ---- persistent device scratch ----
__device__ float g_sums[NL*NCOL];      // [s*NCOL + c]; col 16 = count
__device__ float g_means[NL*C];        // [s*C + c]
__device__ float g_w[NL];
__device__ float g_ext_nrm;
__device__ double g_int;
__device__ unsigned char g_seg[PTOT];

// ---------------- init ----------------
__global__ void k_init() {
    for (int i = threadIdx.x; i < NL*NCOL; i += 1024) g_sums[i] = 0.f;
    if (threadIdx.x == 0) g_int = 0.0;
}

// ---------------- k_seg: labels + counts (no atomics in hot path) ------------
__global__ __launch_bounds__(256) void k_seg(const int* __restrict__ trgt,
                                             const int* __restrict__ mask) {
    extern __shared__ int cnt[];            // [w*2048 + s*32 + lane] : bank = lane
    __shared__ int red[256];
    const int tid = threadIdx.x;
    const int w = tid >> 5, l = tid & 31;
    for (int i = tid; i < NW*2048; i += 256) cnt[i] = 0;
    __syncthreads();

    int* mycnt = cnt + w*2048 + l;
    const size_t base = (size_t)blockIdx.x * SEG_VOX;
    #pragma unroll
    for (int j = 0; j < 8; ++j) {
        size_t off = base + ((size_t)j*256 + tid)*4;
        int4 t4 = *reinterpret_cast<const int4*>(trgt + off);
        int4 m4 = *reinterpret_cast<const int4*>(mask + off);
        int s0 = (m4.x > 0) ? t4.x : 0;
        int s1 = (m4.y > 0) ? t4.y : 0;
        int s2 = (m4.z > 0) ? t4.z : 0;
        int s3 = (m4.w > 0) ? t4.w : 0;
        *reinterpret_cast<uchar4*>(g_seg + off) =
            make_uchar4((unsigned char)s0, (unsigned char)s1,
                        (unsigned char)s2, (unsigned char)s3);
        mycnt[s0*32]++;
        mycnt[s1*32]++;
        mycnt[s2*32]++;
        mycnt[s3*32]++;
    }
    __syncthreads();

    // reduce 256 copies per bin: thread t -> bin s = t/4, part = t%4 (2 warps each)
    const int s = tid >> 2, part = tid & 3;
    int acc = 0;
    for (int ww = part*2; ww < part*2 + 2; ++ww)
        #pragma unroll
        for (int ll = 0; ll < 32; ++ll)
            acc += cnt[ww*2048 + s*32 + ll];
    red[tid] = acc;
    __syncthreads();
    if (part == 0) {
        int tot = red[tid] + red[tid+1] + red[tid+2] + red[tid+3];
        atomicAdd(&g_sums[s*NCOL + 16], (float)tot);
    }
}

// ---------------- pass 1: race-free private-bucket segment sums ----------------
__global__ __launch_bounds__(P1_THREADS) void k_pass1(const float* __restrict__ embd) {
    extern __shared__ float sm[];
    float* bkt = sm;                                    // [w][s*32 + c*2 + h]
    float* xt  = sm + BKT_WORDS;                        // [c][v] stride XT_STRIDE
    unsigned char* segt = (unsigned char*)(sm + BKT_WORDS + XT_WORDS);  // 512 B

    const int tid = threadIdx.x;
    const int w = tid >> 5, l = tid & 31;
    const int h = l >> 4, c = l & 15;

    for (int i = tid; i < BKT_WORDS; i += P1_THREADS) bkt[i] = 0.f;

    const size_t cta_base = (size_t)blockIdx.x * VOX_PER_CTA;

    // prefetch tile 0 into registers (warp w stages channels 2w, 2w+1)
    float2 rx[16];
    unsigned short rseg;
    {
        #pragma unroll
        for (int cc = 0; cc < 2; ++cc) {
            const float* src = embd + (size_t)(2*w + cc)*PTOT + cta_base + 2*l;
            #pragma unroll
            for (int j = 0; j < 8; ++j)
                rx[cc*8 + j] = *reinterpret_cast<const float2*>(src + 64*j);
        }
        rseg = *reinterpret_cast<const unsigned short*>(g_seg + cta_base + 2*tid);
    }
    __syncthreads();   // buckets zeroed

    for (int t = 0; t < NTILES; ++t) {
        // stage registers -> shared tile
        #pragma unroll
        for (int cc = 0; cc < 2; ++cc) {
            float* dst = xt + (2*w + cc)*XT_STRIDE + 2*l;
            #pragma unroll
            for (int j = 0; j < 8; ++j)
                *reinterpret_cast<float2*>(dst + 64*j) = rx[cc*8 + j];
        }
        *reinterpret_cast<unsigned short*>(segt + 2*tid) = rseg;
        __syncthreads();

        // prefetch next tile (LDGs overlap bucket phase)
        if (t + 1 < NTILES) {
            const size_t vb = cta_base + (size_t)(t + 1)*TILE_V;
            #pragma unroll
            for (int cc = 0; cc < 2; ++cc) {
                const float* src = embd + (size_t)(2*w + cc)*PTOT + vb + 2*l;
                #pragma unroll
                for (int j = 0; j < 8; ++j)
                    rx[cc*8 + j] = *reinterpret_cast<const float2*>(src + 64*j);
            }
            rseg = *reinterpret_cast<const unsigned short*>(g_seg + vb + 2*tid);
        }

        // bucket phase: warp w owns voxels [w*64, w*64+64); lane = (h, c)
        {
            const unsigned char* sp = segt + w*64 + h;
            const float* xp = xt + c*XT_STRIDE + w*64 + h;
            float* wb = bkt + w*BKT_WPW + c*2 + h;
            #pragma unroll 4
            for (int p = 0; p < 32; ++p) {
                int s = sp[2*p];
                float x = xp[2*p];
                wb[s*32] += x;      // LDS/FADD/STS, zero bank conflicts, lane-private
            }
        }
        __syncthreads();
    }

    // flush: sum 16 copies per (s,c), one global atomic each
    for (int f = tid; f < NL*C; f += P1_THREADS) {
        const int s = f >> 4, cc = f & 15;
        float acc = 0.f;
        #pragma unroll
        for (int ww = 0; ww < NW; ++ww) {
            acc += bkt[ww*BKT_WPW + s*32 + cc*2 + 0];
            acc += bkt[ww*BKT_WPW + s*32 + cc*2 + 1];
        }
        atomicAdd(&g_sums[s*NCOL + cc], acc);
    }
}

// ---------------- stats ----------------
__global__ void k_stats() {
    __shared__ float sm[NL][C];
    __shared__ float sext[NL];
    __shared__ float snrm[NL];
    __shared__ int   spres[NL];
    __shared__ float sK;
    int s = threadIdx.x;                // 64 threads
    float cnt  = g_sums[s*NCOL + 16];
    int   pres = (cnt > 0.f) && (s != 0);
    float safe = fmaxf(cnt, 1.f);
    #pragma unroll
    for (int c = 0; c < C; c++) {
        float m = g_sums[s*NCOL + c] / safe;
        sm[s][c] = m;
        g_means[s*C + c] = m;
    }
    spres[s] = pres;
    __syncthreads();
    if (s == 0) {
        int k = 0;
        for (int l = 0; l < NL; l++) k += spres[l];
        sK = (float)k;
    }
    __syncthreads();
    float K = sK;
    g_w[s] = pres ? 1.f / (safe * fmaxf(K, 1.f)) : 0.f;

    float nrm = 0.f, ext = 0.f;
    if (pres) {
        #pragma unroll
        for (int c = 0; c < C; c++) nrm += fabsf(sm[s][c]);
        for (int j = 0; j < NL; j++) {
            if (j != s && spres[j]) {
                float d = 0.f;
                #pragma unroll
                for (int c = 0; c < C; c++) d += fabsf(sm[s][c] - sm[j][c]);
                float m = fmaxf(3.0f - d, 0.f);   // 2*DELTA_D
                ext += m * m;
            }
        }
    }
    sext[s] = ext; snrm[s] = nrm;
    __syncthreads();
    if (s == 0) {
        float esum = 0.f, nsum = 0.f;
        for (int l = 0; l < NL; l++) { esum += sext[l]; nsum += snrm[l]; }
        float loss_ext = esum / fmaxf(1.f, K * (K - 1.f));
        float loss_nrm = nsum / fmaxf(1.f, K);
        g_ext_nrm = 1.0f * loss_ext + 0.001f * loss_nrm;
    }
}

// ---------------- pass 2: internal term ----------------
__global__ __launch_bounds__(256) void k_pass2(const float* __restrict__ embd) {
    __shared__ float smean[NL*C];
    __shared__ float sw[NL];
    __shared__ float sred[256];
    int tid = threadIdx.x;
    for (int i = tid; i < NL*C; i += 256) smean[i] = g_means[i];
    if (tid < NL) sw[tid] = g_w[tid];
    __syncthreads();

    size_t base = ((size_t)blockIdx.x * 256 + tid) * 4;
    uchar4 sv = *reinterpret_cast<const uchar4*>(g_seg + base);
    const float4* m0 = reinterpret_cast<const float4*>(&smean[sv.x * C]);
    const float4* m1 = reinterpret_cast<const float4*>(&smean[sv.y * C]);
    const float4* m2 = reinterpret_cast<const float4*>(&smean[sv.z * C]);
    const float4* m3 = reinterpret_cast<const float4*>(&smean[sv.w * C]);

    float g0 = 0.f, g1 = 0.f, g2 = 0.f, g3 = 0.f;
    #pragma unroll
    for (int cg = 0; cg < 4; cg++) {
        float4 a0 = m0[cg], a1 = m1[cg], a2 = m2[cg], a3 = m3[cg];
        float4 v0 = *reinterpret_cast<const float4*>(embd + (size_t)(cg*4+0) * PTOT + base);
        float4 v1 = *reinterpret_cast<const float4*>(embd + (size_t)(cg*4+1) * PTOT + base);
        float4 v2 = *reinterpret_cast<const float4*>(embd + (size_t)(cg*4+2) * PTOT + base);
        float4 v3 = *reinterpret_cast<const float4*>(embd + (size_t)(cg*4+3) * PTOT + base);
        g0 += fabsf(v0.x - a0.x) + fabsf(v1.x - a0.y) + fabsf(v2.x - a0.z) + fabsf(v3.x - a0.w);
        g1 += fabsf(v0.y - a1.x) + fabsf(v1.y - a1.y) + fabsf(v2.y - a1.z) + fabsf(v3.y - a1.w);
        g2 += fabsf(v0.z - a2.x) + fabsf(v1.z - a2.y) + fabsf(v2.z - a2.z) + fabsf(v3.z - a2.w);
        g3 += fabsf(v0.w - a3.x) + fabsf(v1.w - a3.y) + fabsf(v2.w - a3.z) + fabsf(v3.w - a3.w);
    }
    float acc = sw[sv.x]*g0*g0 + sw[sv.y]*g1*g1 + sw[sv.z]*g2*g2 + sw[sv.w]*g3*g3;

    sred[tid] = acc;
    __syncthreads();
    #pragma unroll
    for (int off = 128; off > 0; off >>= 1) {
        if (tid < off) sred[tid] += sred[tid + off];
        __syncthreads();
    }
    if (tid == 0) atomicAdd(&g_int, (double)sred[0]);
}

// ---------------- final combine ----------------
__global__ void k_final(float* out) {
    out[0] = (float)g_int + g_ext_nrm;
}

extern "C" void kernel_launch(void* const* d_in, const int* in_sizes, int n_in,
                              void* d_out, int out_size) {
    const float* embd = (const float*)d_in[0];
    const int*   trgt = (const int*)d_in[1];
    const int*   mask = (const int*)d_in[2];
    float* out = (float*)d_out;

    static int configured = 0;
    if (!configured) {
        cudaFuncSetAttribute(k_pass1, cudaFuncAttributeMaxDynamicSharedMemorySize, P1_SMEM_BYTES);
        cudaFuncSetAttribute(k_seg,   cudaFuncAttributeMaxDynamicSharedMemorySize, SEG_SMEM_BYTES);
        configured = 1;
    }

    k_init <<<1, 1024>>>();
    k_seg  <<<SEG_BLOCKS, 256, SEG_SMEM_BYTES>>>(trgt, mask);
    k_pass1<<<P1_BLOCKS, P1_THREADS, P1_SMEM_BYTES>>>(embd);
    k_stats<<<1, NL>>>();
    k_pass2<<<PTOT/1024, 256>>>(embd);
    k_final<<<1, 1>>>(out);
}